// round 15
// baseline (speedup 1.0000x reference)
#include <cuda_runtime.h>
#include <math.h>

#define NBINS 64
#define BATCH 4
#define NVOX 262144           // 64*64*64
#define HIST_SIZE (NBINS*NBINS)
#define HBLOCKS 148           // 148*4 = 592 = 4 blocks/SM on 148 SMs
#define HTHREADS 256
#define TOTBLK (HBLOCKS * BATCH)
#define MMBLOCKS 64           // minmax_init blocks

#define ROWS_P 68             // padded rows: bins -1..66
#define ULLS_R 18             // ulls per row (max packed col 70 -> idx 17)
#define LAY_ULLS (ROWS_P * ULLS_R)
typedef unsigned long long ull;

#define QSCALE 128.0f                    // per-factor quantization scale
#define INV_FSCALE (1.0f / 16384.0f)     // product scale = 128*128

__device__ float4 g_partial[MMBLOCKS];       // per-block {tmin,tmax,smin,smax}
__device__ float g_hist[BATCH * HIST_SIZE];  // per-batch joint histograms
__device__ unsigned g_done;                  // hist completion ticket

// ---- fused: zero accumulators + per-block minmax partials (no atomics) ----
__global__ void minmax_init_kernel(const float4* __restrict__ t,
                                   const float4* __restrict__ s) {
    const int tid = threadIdx.x;
    const int gid = blockIdx.x * blockDim.x + tid;

    // zero g_hist: 64*256 = 16384 threads cover it exactly
    g_hist[gid] = 0.0f;
    if (gid == 0) g_done = 0u;

    // grid-stride minmax over both tensors
    const int n4 = BATCH * NVOX / 4;
    float tmn = INFINITY, tmx = -INFINITY, smn = INFINITY, smx = -INFINITY;
    for (int i = gid; i < n4; i += MMBLOCKS * HTHREADS) {
        float4 a = t[i];
        tmn = fminf(tmn, fminf(fminf(a.x, a.y), fminf(a.z, a.w)));
        tmx = fmaxf(tmx, fmaxf(fmaxf(a.x, a.y), fmaxf(a.z, a.w)));
        float4 b = s[i];
        smn = fminf(smn, fminf(fminf(b.x, b.y), fminf(b.z, b.w)));
        smx = fmaxf(smx, fmaxf(fmaxf(b.x, b.y), fmaxf(b.z, b.w)));
    }
#pragma unroll
    for (int o = 16; o > 0; o >>= 1) {
        tmn = fminf(tmn, __shfl_xor_sync(0xFFFFFFFFu, tmn, o));
        tmx = fmaxf(tmx, __shfl_xor_sync(0xFFFFFFFFu, tmx, o));
        smn = fminf(smn, __shfl_xor_sync(0xFFFFFFFFu, smn, o));
        smx = fmaxf(smx, __shfl_xor_sync(0xFFFFFFFFu, smx, o));
    }
    __shared__ float sw[4][8];
    const int warp = tid >> 5, lane = tid & 31;
    if (lane == 0) {
        sw[0][warp] = tmn; sw[1][warp] = tmx;
        sw[2][warp] = smn; sw[3][warp] = smx;
    }
    __syncthreads();
    if (tid == 0) {
        float a = sw[0][0], bmx = sw[1][0], c = sw[2][0], d = sw[3][0];
#pragma unroll
        for (int w = 1; w < 8; w++) {
            a = fminf(a, sw[0][w]); bmx = fmaxf(bmx, sw[1][w]);
            c = fminf(c, sw[2][w]); d = fmaxf(d, sw[3][w]);
        }
        g_partial[blockIdx.x] = make_float4(a, bmx, c, d);
    }
}

// 4-tap cubic B-spline weights for fractional position f in [0,1).
__device__ __forceinline__ void bsw(float f, float w[4]) {
    float omf = 1.0f - f;
    w[0] = omf * omf * omf * (1.0f / 6.0f);
    w[1] = (2.0f / 3.0f) - f * f + 0.5f * f * f * f;
    w[2] = (2.0f / 3.0f) - omf * omf + 0.5f * omf * omf * omf;
    w[3] = f * f * f * (1.0f / 6.0f);
}

// extract 16-bit lane l from ull
__device__ __forceinline__ unsigned lane16(ull v, int l) {
    return (unsigned)((v >> (l * 16)) & 0xFFFFull);
}

__global__ void hist_kernel(const float* __restrict__ t,
                            const float* __restrict__ s,
                            float* __restrict__ out) {
    // Four parity-shifted 16-bit x4 fixed-point layouts: layout j stores
    // padded col p in ull (p+j)>>2, lane (p+j)&3. A voxel picks j = (-p0)&3
    // so its 4-col window is one aligned ull -> 1 atomic per row, 4/voxel.
    // Row word = single integer multiply Q*round(wt[a]*128); lane products
    // <= 8100 so the 64-bit multiply is carry-free across 16-bit lanes.
    __shared__ ull lay[4][LAY_ULLS];
    __shared__ float s_mm[4];
    const int b = blockIdx.y;
    for (int i = threadIdx.x; i < 4 * LAY_ULLS; i += blockDim.x)
        lay[0][i] = 0ull;

    // reduce the 64 minmax partials (warp 0; L2-resident after first block)
    if (threadIdx.x < 32) {
        float tmn = INFINITY, tmx = -INFINITY, smn = INFINITY, smx = -INFINITY;
        for (int i = threadIdx.x; i < MMBLOCKS; i += 32) {
            float4 p = g_partial[i];
            tmn = fminf(tmn, p.x); tmx = fmaxf(tmx, p.y);
            smn = fminf(smn, p.z); smx = fmaxf(smx, p.w);
        }
#pragma unroll
        for (int o = 16; o > 0; o >>= 1) {
            tmn = fminf(tmn, __shfl_xor_sync(0xFFFFFFFFu, tmn, o));
            tmx = fmaxf(tmx, __shfl_xor_sync(0xFFFFFFFFu, tmx, o));
            smn = fminf(smn, __shfl_xor_sync(0xFFFFFFFFu, smn, o));
            smx = fmaxf(smx, __shfl_xor_sync(0xFFFFFFFFu, smx, o));
        }
        if (threadIdx.x == 0) {
            s_mm[0] = tmn; s_mm[1] = tmx; s_mm[2] = smn; s_mm[3] = smx;
        }
    }
    __syncthreads();

    const float tmn = s_mm[0], tmx = s_mm[1];
    const float smn = s_mm[2], smx = s_mm[3];
    const float tsc = 64.0f / (tmx - tmn + 1e-12f);
    const float ssc = 64.0f / (smx - smn + 1e-12f);

    const float4* tb = (const float4*)(t + (size_t)b * NVOX);
    const float4* sb = (const float4*)(s + (size_t)b * NVOX);
    const int n4 = NVOX / 4;

    for (int v = blockIdx.x * blockDim.x + threadIdx.x; v < n4;
         v += gridDim.x * blockDim.x) {
        float4 tv = tb[v];
        float4 sv = sb[v];
        float tvals[4] = {tv.x, tv.y, tv.z, tv.w};
        float svals[4] = {sv.x, sv.y, sv.z, sv.w};
#pragma unroll
        for (int k = 0; k < 4; k++) {
            float xt = (tvals[k] - tmn) * tsc;
            float xs = (svals[k] - smn) * ssc;
            int it = (int)floorf(xt);
            int is = (int)floorf(xs);
            float ft = xt - (float)it;
            float fs = xs - (float)is;
            float wt[4], ws[4];
            bsw(ft, wt);
            bsw(fs, ws);
            ull q0 = (ull)__float2uint_rn(ws[0] * QSCALE);
            ull q1 = (ull)__float2uint_rn(ws[1] * QSCALE);
            ull q2 = (ull)__float2uint_rn(ws[2] * QSCALE);
            ull q3 = (ull)__float2uint_rn(ws[3] * QSCALE);
            ull Q = q0 | (q1 << 16) | (q2 << 32) | (q3 << 48);
            const int j = (-is) & 3;
            ull* L = lay[j] + ((is + j) >> 2);
#pragma unroll
            for (int a = 0; a < 4; a++) {
                ull wa = (ull)__float2uint_rn(wt[a] * QSCALE);
                atomicAdd(L + (it + a) * ULLS_R, Q * wa);
            }
        }
    }
    __syncthreads();

    // flush joint hist ONLY: bin (r,c) -> padded (rr=r+1, p=c+1)
    float* gh = g_hist + b * HIST_SIZE;
    for (int i = threadIdx.x; i < HIST_SIZE; i += blockDim.x) {
        int r = i >> 6, c = i & 63;
        int rr = r + 1, p = c + 1;
        unsigned u = 0;
#pragma unroll
        for (int j = 0; j < 4; j++) {
            int pj = p + j;
            u += lane16(lay[j][rr * ULLS_R + (pj >> 2)], pj & 3);
        }
        if (u) atomicAdd(&gh[i], (float)u * INV_FSCALE);
    }

    // ---- last-block-done finalization ----
    __threadfence();
    __shared__ unsigned isLast;
    if (threadIdx.x == 0)
        isLast = (atomicAdd(&g_done, 1u) == (unsigned)(TOTBLK - 1));
    __syncthreads();
    if (!isLast) return;
    __threadfence();  // acquire: all blocks' flushes visible

    const int tid = threadIdx.x;
    const int warp = tid >> 5, lane = tid & 31;
    __shared__ float shS;
    __shared__ float shHj[BATCH];
    __shared__ float shE[BATCH];
    __shared__ float shwsum[8];
    if (tid < BATCH) { shHj[tid] = 0.0f; shE[tid] = 0.0f; }

    // marginals straight from g_hist (L2-hot): thread owns (mb, mbin)
    const int mb = tid >> 6, mbin = tid & 63;
    const float* hb = g_hist + mb * HIST_SIZE;

    // row sum: 16 contiguous float4 loads
    float rsum = 0.0f;
    {
        const float4* rp = (const float4*)(hb + mbin * NBINS);
#pragma unroll
        for (int x = 0; x < 16; x++) {
            float4 q = rp[x];
            rsum += (q.x + q.y) + (q.z + q.w);
        }
    }
    // col sum: 64 independent stride-64 loads
    float csum = 0.0f;
#pragma unroll 8
    for (int r = 0; r < NBINS; r++) csum += hb[r * NBINS + mbin];

    // S = sum of all row sums
    {
        float v = rsum;
#pragma unroll
        for (int o = 16; o > 0; o >>= 1) v += __shfl_xor_sync(0xFFFFFFFFu, v, o);
        if (lane == 0) shwsum[warp] = v;
    }
    __syncthreads();
    if (tid == 0) {
        float x = 0.0f;
#pragma unroll
        for (int w = 0; w < 8; w++) x += shwsum[w];
        shS = x;
    }
    __syncthreads();
    const float inv = 1.0f / shS;

    // marginal entropy terms (mb uniform per warp: warps 2b, 2b+1)
    {
        float pr = rsum * inv, pc = csum * inv;
        float e = pr * __logf(pr + 1e-12f) + pc * __logf(pc + 1e-12f);
#pragma unroll
        for (int o = 16; o > 0; o >>= 1) e += __shfl_xor_sync(0xFFFFFFFFu, e, o);
        if (lane == 0) atomicAdd(&shE[mb], e);
    }

    // joint entropy: coalesced float4 pass; batch = k>>2, uniform per warp
    const float4* g4 = (const float4*)g_hist;
    float acc[BATCH] = {0.0f, 0.0f, 0.0f, 0.0f};
#pragma unroll
    for (int k = 0; k < 16; k++) {
        float4 q = g4[k * 256 + tid];
        float p0 = q.x * inv, p1 = q.y * inv, p2 = q.z * inv, p3 = q.w * inv;
        acc[k >> 2] += p0 * __logf(p0 + 1e-12f) + p1 * __logf(p1 + 1e-12f) +
                       p2 * __logf(p2 + 1e-12f) + p3 * __logf(p3 + 1e-12f);
    }
#pragma unroll
    for (int bb = 0; bb < BATCH; bb++) {
        float x = acc[bb];
#pragma unroll
        for (int o = 16; o > 0; o >>= 1) x += __shfl_xor_sync(0xFFFFFFFFu, x, o);
        if (lane == 0) atomicAdd(&shHj[bb], x);
    }
    __syncthreads();
    if (tid == 0) {
        float total = 0.0f;
#pragma unroll
        for (int bb = 0; bb < BATCH; bb++) total += shE[bb] / shHj[bb];
        out[0] = -total / (float)BATCH;  // (-E)/(-Hj) = E/Hj
    }
}

extern "C" void kernel_launch(void* const* d_in, const int* in_sizes, int n_in,
                              void* d_out, int out_size) {
    const float* target = (const float*)d_in[0];
    const float* source = (const float*)d_in[1];
    float* out = (float*)d_out;

    minmax_init_kernel<<<MMBLOCKS, HTHREADS>>>((const float4*)target,
                                               (const float4*)source);
    {
        dim3 grid(HBLOCKS, BATCH);
        hist_kernel<<<grid, HTHREADS>>>(target, source, out);
    }
}